// round 17
// baseline (speedup 1.0000x reference)
#include <cuda_runtime.h>
#include <math.h>

// FFF: fast-feedforward conditional tree MLP.
// B=8192, D_in=D_out=2048, depth 11 -> 12 routing steps, 4095 nodes.
//
// k1 transpose_wout: W_out -> g_WoutT on a forked stream (overlaps route).
// k2 route_kernel:   32-thread block = ONE warp = one sample. 16 blocks/SM
//                    (launch_bounds(32,16) -> full 128-reg budget, no spill).
//                    x = 16 float4/lane in regs; per step: 16 LDG.128 ->
//                    4 independent dot partials -> 5-shfl xor butterfly
//                    (bit-deterministic, all lanes converge). No smem, no
//                    __syncthreads -> short chain, 16 decorrelated chains/SM.
// k3 out_kernel:     out[b] = sum_d g_d * W_outT[node_d]; latency-immune.

#define DEPTH    11
#define NSTEPS   (DEPTH + 1)
#define N_NODES  4095
#define DDIM     2048
#define D4       (DDIM / 4)     // 512 float4 per row
#define BATCH    8192

__device__ float g_WoutT[(size_t)N_NODES * DDIM];
__device__ int   g_nodes[(size_t)BATCH * NSTEPS];
__device__ float g_gval [(size_t)BATCH * NSTEPS];

// 64x64 tile transpose, 256 threads, coalesced both sides.
__global__ __launch_bounds__(256) void transpose_wout(const float* __restrict__ Wout) {
    __shared__ float tile[64][65];
    const int n0 = blockIdx.x * 64;
    const int o0 = blockIdx.y * 64;
    const int tid = threadIdx.x;

    #pragma unroll
    for (int k = 0; k < 16; ++k) {
        int e = k * 256 + tid;
        int ol = e >> 6;
        int nl = e & 63;
        int n = n0 + nl;
        float v = 0.f;
        if (n < N_NODES)
            v = Wout[(size_t)(o0 + ol) * N_NODES + n];
        tile[nl][ol] = v;
    }
    __syncthreads();

    #pragma unroll
    for (int k = 0; k < 16; ++k) {
        int e = k * 256 + tid;
        int nl = e >> 6;
        int ol = e & 63;
        int n = n0 + nl;
        if (n < N_NODES)
            g_WoutT[(size_t)n * DDIM + (o0 + ol)] = tile[nl][ol];
    }
}

__device__ __forceinline__ float dot4(float4 a, float4 b) {
    return fmaf(a.x, b.x, fmaf(a.y, b.y, fmaf(a.z, b.z, a.w * b.w)));
}

__device__ __forceinline__ void fma4(float4& a, float g, float4 v) {
    a.x = fmaf(g, v.x, a.x);
    a.y = fmaf(g, v.y, a.y);
    a.z = fmaf(g, v.z, a.z);
    a.w = fmaf(g, v.w, a.w);
}

__device__ __forceinline__ float gelu_exact(float s) {
    return 0.5f * s * (1.0f + erff(s * 0.70710678118654752f));
}

// One warp per sample; 16 warp-blocks per SM.
__global__ __launch_bounds__(32, 16) void route_kernel(
    const float* __restrict__ x,
    const float* __restrict__ Win)
{
    const int b    = blockIdx.x;
    const int lane = threadIdx.x;

    const float4* __restrict__ Win4 = reinterpret_cast<const float4*>(Win);
    const float4* __restrict__ x4   = reinterpret_cast<const float4*>(x) + (size_t)b * D4;

    // x row: 16 float4 per lane (lane + 32*i), fully coalesced.
    float4 xr[16];
    #pragma unroll
    for (int i = 0; i < 16; ++i)
        xr[i] = x4[lane + 32 * i];

    int node = 0;
    #pragma unroll
    for (int d = 0; d < NSTEPS; ++d) {
        const float4* __restrict__ wr = Win4 + (size_t)node * D4 + lane;

        // 4 independent partial sums -> ILP in the FMA chain.
        float p0 = 0.f, p1 = 0.f, p2 = 0.f, p3 = 0.f;
        #pragma unroll
        for (int i = 0; i < 16; i += 4) {
            p0 += dot4(wr[32 * i],        xr[i]);
            p1 += dot4(wr[32 * (i + 1)],  xr[i + 1]);
            p2 += dot4(wr[32 * (i + 2)],  xr[i + 2]);
            p3 += dot4(wr[32 * (i + 3)],  xr[i + 3]);
        }
        float p = (p0 + p1) + (p2 + p3);

        // XOR butterfly: identical pair-tree on every lane -> bit-identical
        // warp sum on all 32 lanes, no broadcast needed.
        #pragma unroll
        for (int off = 16; off > 0; off >>= 1)
            p += __shfl_xor_sync(0xffffffffu, p, off);

        if (lane == 0) {
            g_nodes[(size_t)b * NSTEPS + d] = node;
            g_gval [(size_t)b * NSTEPS + d] = gelu_exact(p);
        }

        node = node * 2 + 1 + (p >= 0.0f ? 1 : 0);
    }
}

// Output accumulation: fully parallel, 12 independent row gathers per sample.
__global__ __launch_bounds__(128, 8) void out_kernel(
    float* __restrict__ out)
{
    const int b   = blockIdx.x;
    const int tid = threadIdx.x;

    const float4* __restrict__ Wt4 = reinterpret_cast<const float4*>(g_WoutT);

    int   nd[NSTEPS];
    float gg[NSTEPS];
    #pragma unroll
    for (int d = 0; d < NSTEPS; ++d) {
        nd[d] = g_nodes[(size_t)b * NSTEPS + d];
        gg[d] = g_gval [(size_t)b * NSTEPS + d];
    }

    float4 a0 = make_float4(0.f, 0.f, 0.f, 0.f);
    float4 a1 = make_float4(0.f, 0.f, 0.f, 0.f);
    float4 a2 = make_float4(0.f, 0.f, 0.f, 0.f);
    float4 a3 = make_float4(0.f, 0.f, 0.f, 0.f);

    #pragma unroll
    for (int d = 0; d < NSTEPS; ++d) {
        const float4* __restrict__ vr = Wt4 + (size_t)nd[d] * D4;
        float g = gg[d];
        fma4(a0, g, vr[tid]);
        fma4(a1, g, vr[tid + 128]);
        fma4(a2, g, vr[tid + 256]);
        fma4(a3, g, vr[tid + 384]);
    }

    float4* __restrict__ o4 = reinterpret_cast<float4*>(out) + (size_t)b * D4;
    o4[tid]       = a0;
    o4[tid + 128] = a1;
    o4[tid + 256] = a2;
    o4[tid + 384] = a3;
}

extern "C" void kernel_launch(void* const* d_in, const int* in_sizes, int n_in,
                              void* d_out, int out_size)
{
    const float* x    = (const float*)d_in[0];   // (8192, 2048)
    const float* Win  = (const float*)d_in[1];   // (4095, 2048)
    const float* Wout = (const float*)d_in[2];   // (2048, 4095)
    float* out = (float*)d_out;                  // (8192, 2048)

    cudaStream_t s2;
    cudaStreamCreateWithFlags(&s2, cudaStreamNonBlocking);
    cudaEvent_t eFork, eJoin;
    cudaEventCreateWithFlags(&eFork, cudaEventDisableTiming);
    cudaEventCreateWithFlags(&eJoin, cudaEventDisableTiming);

    // Fork: transpose (W_out only) overlaps route (x, W_in).
    cudaEventRecord(eFork, 0);
    cudaStreamWaitEvent(s2, eFork, 0);
    dim3 tg((N_NODES + 63) / 64, DDIM / 64);
    transpose_wout<<<tg, 256, 0, s2>>>(Wout);
    cudaEventRecord(eJoin, s2);

    route_kernel<<<BATCH, 32>>>(x, Win);

    cudaStreamWaitEvent(0, eJoin, 0);
    out_kernel<<<BATCH, 128>>>(out);
}